// round 8
// baseline (speedup 1.0000x reference)
#include <cuda_runtime.h>
#include <cstdint>

#define THRESH 0.85f
#define NB 4
#define ND 16
#define NN 4096
#define KC 32                 // K per chunk
#define NCH (NN / KC)         // 128 chunks
#define NSEG 24               // padded N: 16 d + ones col + 7 zero (mult of 8)
#define MT 128                // M rows per CTA
#define STRA 36               // smem row stride in floats (4r+c bank spread)

// S matrix: [b][24][4096]; rows 0-15 = tf32(seg), row 16 = ones, 17-23 = 0
__device__ float g_S[NB * NSEG * NN];

__device__ __forceinline__ uint32_t cvt_tf32(float x) {
    uint32_t u; asm("cvt.rna.tf32.f32 %0, %1;" : "=r"(u) : "f"(x));
    return u;
}

__device__ __forceinline__ void mma_tf32(float (&c)[4], uint32_t a0, uint32_t a1,
                                         uint32_t a2, uint32_t a3,
                                         uint32_t b0, uint32_t b1) {
    asm volatile(
        "mma.sync.aligned.m16n8k8.row.col.f32.tf32.tf32.f32 "
        "{%0,%1,%2,%3}, {%4,%5,%6,%7}, {%8,%9}, {%0,%1,%2,%3};"
        : "+f"(c[0]), "+f"(c[1]), "+f"(c[2]), "+f"(c[3])
        : "r"(a0), "r"(a1), "r"(a2), "r"(a3), "r"(b0), "r"(b1));
}

// ---------------- prologue: S = [tf32(seg) | ones | zeros], [b][n][k] ----------------
__global__ void __launch_bounds__(256) build_s_kernel(const float* __restrict__ seg) {
    int idx = blockIdx.x * 256 + threadIdx.x;     // 0 .. NB*NSEG*NN-1
    int n   = idx & (NN - 1);
    int t   = idx >> 12;                          // b*NSEG + row
    int row = t % NSEG;
    int b   = t / NSEG;
    float v;
    if (row < ND)        v = __uint_as_float(cvt_tf32(seg[(((size_t)b * ND + row) << 12) + n]));
    else if (row == ND)  v = 1.0f;
    else                 v = 0.0f;
    g_S[idx] = v;
}

// ---------------- main kernel ----------------
// grid = 128 CTAs (4 b x 32 M-tiles of 128 rows), block = 256 thr = 8 warps.
// Warp w owns rows w*16..w*16+15 of the tile. K loop in 32-chunks:
// coalesced LDG.128 -> threshold+tf32 in regs -> STS (stride-36) ->
// m16n8k8 tf32 HMMA (A frag LDS conflict-free; B frags shared).
__global__ void __launch_bounds__(256, 1) regu_mma_kernel(const float* __restrict__ W,
                                                          float* __restrict__ out) {
    __shared__ __align__(16) float sA[2][MT * STRA];    // 2 x 18KB thresholded W (tf32)
    __shared__ __align__(16) float sB[2][NSEG * STRA];  // 2 x 3.4KB S chunk

    const int tid  = threadIdx.x;
    const int w    = tid >> 5;
    const int lane = tid & 31;
    const int gr   = lane >> 2;       // group (row within fragment)
    const int tg   = lane & 3;        // thread-in-group (col)
    const int b     = blockIdx.x >> 5;
    const int mbase = (blockIdx.x & 31) << 7;

    const float* Wp = W + ((size_t)(b * NN + mbase)) * NN;
    const float* Sp = g_S + (size_t)b * NSEG * NN;

    // B staging coords: NSEG(24) rows x 8 float4 per row = 192 threads
    const int bn  = tid >> 3;         // row (0..23 valid when tid<192)
    const int bk4 = tid & 7;          // float4 index within KC=32

    float4 rW[2][4]; float4 rS[2];
#pragma unroll
    for (int pp = 0; pp < 2; ++pp) {
#pragma unroll
        for (int f = 0; f < 4; ++f) {
            int idx = f * 256 + tid;
            int row = idx >> 3, c4 = idx & 7;
            rW[pp][f] = __ldg(reinterpret_cast<const float4*>(
                Wp + (size_t)row * NN + pp * KC + c4 * 4));
        }
        if (tid < 192)
            rS[pp] = __ldg(reinterpret_cast<const float4*>(
                Sp + (size_t)bn * NN + pp * KC + bk4 * 4));
    }

    float acc[3][4];
#pragma unroll
    for (int nt = 0; nt < 3; ++nt)
#pragma unroll
        for (int c = 0; c < 4; ++c) acc[nt][c] = 0.0f;

#pragma unroll 1
    for (int i = 0; i < NCH; ++i) {
        const int p = i & 1;
        // ---- stage: threshold + tf32 + STS ----
        float* sAp = sA[p];
#pragma unroll
        for (int f = 0; f < 4; ++f) {
            int idx = f * 256 + tid;
            int row = idx >> 3, c4 = idx & 7;
            float4 v = rW[p][f];
            uint4 t;
            t.x = cvt_tf32((v.x > THRESH) ? v.x : 0.0f);
            t.y = cvt_tf32((v.y > THRESH) ? v.y : 0.0f);
            t.z = cvt_tf32((v.z > THRESH) ? v.z : 0.0f);
            t.w = cvt_tf32((v.w > THRESH) ? v.w : 0.0f);
            *reinterpret_cast<uint4*>(sAp + row * STRA + c4 * 4) = t;
        }
        if (tid < 192)
            *reinterpret_cast<float4*>(sB[p] + bn * STRA + bk4 * 4) = rS[p];
        // ---- prefetch chunk i+2 ----
        if (i + 2 < NCH) {
            const int kb = (i + 2) * KC;
#pragma unroll
            for (int f = 0; f < 4; ++f) {
                int idx = f * 256 + tid;
                int row = idx >> 3, c4 = idx & 7;
                rW[p][f] = __ldg(reinterpret_cast<const float4*>(
                    Wp + (size_t)row * NN + kb + c4 * 4));
            }
            if (tid < 192)
                rS[p] = __ldg(reinterpret_cast<const float4*>(
                    Sp + (size_t)bn * NN + kb + bk4 * 4));
        }
        __syncthreads();
        // ---- B fragments (k8 x n8, col-major): b0=(k=tg,n=gr), b1=(k=tg+4,n=gr) ----
        uint32_t bf[4][3][2];
        const float* sBp = sB[p];
#pragma unroll
        for (int ks = 0; ks < 4; ++ks)
#pragma unroll
            for (int nt = 0; nt < 3; ++nt) {
                int n = nt * 8 + gr;
                bf[ks][nt][0] = __float_as_uint(sBp[n * STRA + ks * 8 + tg]);
                bf[ks][nt][1] = __float_as_uint(sBp[n * STRA + ks * 8 + tg + 4]);
            }
        // ---- A fragments + MMA ----
        const float* sAr = sA[p] + (w * 16 + gr) * STRA;
#pragma unroll
        for (int ks = 0; ks < 4; ++ks) {
            uint32_t a0 = __float_as_uint(sAr[ks * 8 + tg]);
            uint32_t a1 = __float_as_uint(sAr[8 * STRA + ks * 8 + tg]);
            uint32_t a2 = __float_as_uint(sAr[ks * 8 + tg + 4]);
            uint32_t a3 = __float_as_uint(sAr[8 * STRA + ks * 8 + tg + 4]);
#pragma unroll
            for (int nt = 0; nt < 3; ++nt)
                mma_tf32(acc[nt], a0, a1, a2, a3, bf[ks][nt][0], bf[ks][nt][1]);
        }
        __syncthreads();
    }

    // ---- epilogue: divide by ones-column (n=16 -> tile 2, col 0) ----
    // acc[nt][c]: row = gr + (c>=2 ? 8 : 0), col = nt*8 + 2*tg + (c&1)
    const float den_lo = __shfl_sync(0xffffffffu, acc[2][0], lane & ~3);
    const float den_hi = __shfl_sync(0xffffffffu, acc[2][2], lane & ~3);
    const float inv_lo = 1.0f / den_lo;
    const float inv_hi = 1.0f / den_hi;
    const int m_lo = mbase + w * 16 + gr;
    float* ob = out + (size_t)b * ND * NN;
#pragma unroll
    for (int nt = 0; nt < 2; ++nt) {
#pragma unroll
        for (int c = 0; c < 4; ++c) {
            int d = nt * 8 + 2 * tg + (c & 1);
            int m = m_lo + ((c >= 2) ? 8 : 0);
            ob[(size_t)d * NN + m] = acc[nt][c] * ((c >= 2) ? inv_hi : inv_lo);
        }
    }
}

extern "C" void kernel_launch(void* const* d_in, const int* in_sizes, int n_in,
                              void* d_out, int out_size) {
    const float* seg = (const float*)d_in[0];   // [4,16,64,64] fp32
    const float* W   = (const float*)d_in[1];   // [4,4096,4096] fp32
    float* out = (float*)d_out;                 // [4,16,64,64] fp32
    (void)in_sizes; (void)n_in; (void)out_size;

    build_s_kernel<<<(NB * NSEG * NN) / 256, 256>>>(seg);
    regu_mma_kernel<<<NB * (NN / MT), 256>>>(W, out);
}

// round 9
// speedup vs baseline: 1.0817x; 1.0817x over previous
#include <cuda_runtime.h>
#include <cstdint>

#define THRESH 0.85f
#define NB 4
#define ND 16
#define NN 4096
#define KC 32                  // K per chunk
#define NCH (NN / KC)          // 128 chunks
#define MT 64                  // rows per CTA (4 warps x 16)

// Precomputed B fragments: [b][chunk][frag 0..5][lane 0..31][4 floats]
// value layout per lane: vidx = ks*6 + nt*2 + r  (ks 0..3, nt 0..2, r 0..1)
// -> frag f = vidx>>2, component j = vidx&3
// value = S[n = nt*8+gr][k = chunk*32 + ks*8 + tg + 4r], gr=lane>>2, tg=lane&3
// S rows: 0-15 = tf32(seg[d]), 16 = ones, 17-23 = 0
__device__ float g_Bfrag[NB * NCH * 6 * 32 * 4];   // 1.5 MB

__device__ __forceinline__ uint32_t cvt_tf32(float x) {
    uint32_t u; asm("cvt.rna.tf32.f32 %0, %1;" : "=r"(u) : "f"(x));
    return u;
}

__device__ __forceinline__ void mma_tf32(float (&c)[4], uint32_t a0, uint32_t a1,
                                         uint32_t a2, uint32_t a3,
                                         uint32_t b0, uint32_t b1) {
    asm volatile(
        "mma.sync.aligned.m16n8k8.row.col.f32.tf32.tf32.f32 "
        "{%0,%1,%2,%3}, {%4,%5,%6,%7}, {%8,%9}, {%0,%1,%2,%3};"
        : "+f"(c[0]), "+f"(c[1]), "+f"(c[2]), "+f"(c[3])
        : "r"(a0), "r"(a1), "r"(a2), "r"(a3), "r"(b0), "r"(b1));
}

__device__ __forceinline__ uint32_t f4c(const float4& v, int j) {
    return __float_as_uint(j == 0 ? v.x : j == 1 ? v.y : j == 2 ? v.z : v.w);
}

// ---------------- prologue: build fragment-major B table ----------------
__global__ void __launch_bounds__(256) build_bfrag_kernel(const float* __restrict__ seg) {
    int idx = blockIdx.x * 256 + threadIdx.x;       // 0 .. NB*NCH*6*32*4-1
    int j = idx & 3;
    int l = (idx >> 2) & 31;
    int t = idx >> 7;                               // (b*NCH + c)*6 + f
    int f = t % 6;
    int t2 = t / 6;
    int c = t2 & (NCH - 1);
    int b = t2 >> 7;
    int vidx = 4 * f + j;
    int ks = vidx / 6;
    int rem = vidx - 6 * ks;
    int nt = rem >> 1;
    int r  = rem & 1;
    int gr = l >> 2, tg = l & 3;
    int n = nt * 8 + gr;
    int k = c * KC + ks * 8 + tg + 4 * r;
    float v;
    if (n < ND)       v = __uint_as_float(cvt_tf32(seg[(((size_t)b * ND + n) << 12) + k]));
    else if (n == ND) v = 1.0f;
    else              v = 0.0f;
    g_Bfrag[idx] = v;
}

// ---------------- main kernel ----------------
// grid = 256 CTAs (4 b x 64 tiles of 64 rows), block = 128 thr = 4 warps.
// Each warp autonomously processes 16 rows x K=4096: no __syncthreads in the
// loop. Per chunk: 4 LDG.128 (W, depth-2 prefetch) -> threshold+tf32 ->
// STS to warp-private XOR-swizzled smem -> __syncwarp -> LDS A fragments ->
// 12 HMMA with register-resident precomputed B frags (6 LDG.128, depth-2).
__global__ void __launch_bounds__(128, 4) regu_mma_kernel(const float* __restrict__ W,
                                                          float* __restrict__ out) {
    __shared__ __align__(16) float sA[4][2][16 * 32];   // per-warp double buffer

    const int tid  = threadIdx.x;
    const int w    = tid >> 5;
    const int lane = tid & 31;
    const int gr   = lane >> 2;
    const int tg   = lane & 3;
    const int b     = blockIdx.x >> 6;
    const int mbase = (blockIdx.x & 63) << 6;
    const int rwarp = mbase + w * 16;

    const float* Wp = W + ((size_t)(b * NN + rwarp)) * NN;
    const float* Bf = g_Bfrag + (size_t)b * NCH * 768;

    // W staging coords: q-th LDG covers rows q*4 + (lane>>3), col4 = lane&7
    const int srow = lane >> 3;
    const int sc4  = lane & 7;
    const float* Wq[4];
#pragma unroll
    for (int q = 0; q < 4; ++q)
        Wq[q] = Wp + (size_t)(q * 4 + srow) * NN + sc4 * 4;

    float4 rW[2][4]; float4 rB[2][6];
#pragma unroll
    for (int pp = 0; pp < 2; ++pp) {
#pragma unroll
        for (int q = 0; q < 4; ++q)
            rW[pp][q] = __ldg(reinterpret_cast<const float4*>(Wq[q] + pp * KC));
#pragma unroll
        for (int f = 0; f < 6; ++f)
            rB[pp][f] = __ldg(reinterpret_cast<const float4*>(
                Bf + (size_t)pp * 768 + f * 128 + lane * 4));
    }

    float acc[3][4];
#pragma unroll
    for (int nt = 0; nt < 3; ++nt)
#pragma unroll
        for (int c = 0; c < 4; ++c) acc[nt][c] = 0.0f;

    float* sAw0 = &sA[w][0][0];
    float* sAw1 = &sA[w][1][0];

#pragma unroll 1
    for (int i = 0; i < NCH; ++i) {
        const int p = i & 1;
        float* sb = p ? sAw1 : sAw0;
        // ---- stage chunk i: threshold + tf32 + swizzled STS ----
#pragma unroll
        for (int q = 0; q < 4; ++q) {
            const int row = q * 4 + srow;
            float4 v = rW[p][q];
            uint4 t;
            t.x = cvt_tf32((v.x > THRESH) ? v.x : 0.0f);
            t.y = cvt_tf32((v.y > THRESH) ? v.y : 0.0f);
            t.z = cvt_tf32((v.z > THRESH) ? v.z : 0.0f);
            t.w = cvt_tf32((v.w > THRESH) ? v.w : 0.0f);
            const int phys = row * 32 + ((sc4 ^ (row & 7)) << 2);
            *reinterpret_cast<uint4*>(sb + phys) = t;
        }
        // ---- prefetch W chunk i+2 ----
        if (i + 2 < NCH) {
            const int ko = (i + 2) * KC;
#pragma unroll
            for (int q = 0; q < 4; ++q)
                rW[p][q] = __ldg(reinterpret_cast<const float4*>(Wq[q] + ko));
        }
        __syncwarp();
        // ---- A fragments (swizzled LDS, conflict-free) + MMA ----
#pragma unroll
        for (int ks = 0; ks < 4; ++ks) {
            const int c4a = 2 * ks, c4b = 2 * ks + 1;
            uint32_t a0 = __float_as_uint(sb[gr * 32 + ((c4a ^ gr) << 2) + tg]);
            uint32_t a1 = __float_as_uint(sb[(gr + 8) * 32 + ((c4a ^ gr) << 2) + tg]);
            uint32_t a2 = __float_as_uint(sb[gr * 32 + ((c4b ^ gr) << 2) + tg]);
            uint32_t a3 = __float_as_uint(sb[(gr + 8) * 32 + ((c4b ^ gr) << 2) + tg]);
#pragma unroll
            for (int nt = 0; nt < 3; ++nt) {
                const int v0 = ks * 6 + nt * 2;
                const int v1 = v0 + 1;
                uint32_t b0 = f4c(rB[p][v0 >> 2], v0 & 3);
                uint32_t b1 = f4c(rB[p][v1 >> 2], v1 & 3);
                mma_tf32(acc[nt], a0, a1, a2, a3, b0, b1);
            }
        }
        __syncwarp();
        // ---- prefetch B chunk i+2 (rB[p] fully consumed above) ----
        if (i + 2 < NCH) {
            const float* bp = Bf + (size_t)(i + 2) * 768 + lane * 4;
#pragma unroll
            for (int f = 0; f < 6; ++f)
                rB[p][f] = __ldg(reinterpret_cast<const float4*>(bp + f * 128));
        }
    }

    // ---- epilogue: divide by ones-column (n=16 -> nt=2, col 0) ----
    // acc[nt][c]: row = gr + (c>=2 ? 8 : 0), col = nt*8 + 2*tg + (c&1)
    const float den_lo = __shfl_sync(0xffffffffu, acc[2][0], lane & ~3);
    const float den_hi = __shfl_sync(0xffffffffu, acc[2][2], lane & ~3);
    const float inv_lo = 1.0f / den_lo;
    const float inv_hi = 1.0f / den_hi;
    const int m_lo = rwarp + gr;
    float* ob = out + (size_t)b * ND * NN;
#pragma unroll
    for (int nt = 0; nt < 2; ++nt) {
#pragma unroll
        for (int c = 0; c < 4; ++c) {
            int d = nt * 8 + 2 * tg + (c & 1);
            int m = m_lo + ((c >= 2) ? 8 : 0);
            ob[(size_t)d * NN + m] = acc[nt][c] * ((c >= 2) ? inv_hi : inv_lo);
        }
    }
}

extern "C" void kernel_launch(void* const* d_in, const int* in_sizes, int n_in,
                              void* d_out, int out_size) {
    const float* seg = (const float*)d_in[0];   // [4,16,64,64] fp32
    const float* W   = (const float*)d_in[1];   // [4,4096,4096] fp32
    float* out = (float*)d_out;                 // [4,16,64,64] fp32
    (void)in_sizes; (void)n_in; (void)out_size;

    build_bfrag_kernel<<<(NB * NCH * 6 * 32 * 4) / 256, 256>>>(seg);
    regu_mma_kernel<<<NB * (NN / MT), 128>>>(W, out);
}

// round 10
// speedup vs baseline: 1.3417x; 1.2404x over previous
#include <cuda_runtime.h>
#include <cstdint>

#define THRESH 0.85f
#define NB 4
#define ND 16
#define NN 4096
#define KC 32                  // K per chunk
#define NCH (NN / KC)          // 128 chunks total
#define WCH 32                 // chunks per warp (K-split by 4)

// Precomputed B fragments: [b][chunk][frag 0..5][lane 0..31][4 floats]
// vidx = ks*6 + nt*2 + r -> frag f = vidx>>2, component j = vidx&3
// value = S[n = nt*8+gr][k = chunk*32 + ks*8 + tg + 4r]
// S rows: 0-15 = tf32(seg[d]), 16 = ones, 17-23 = 0
__device__ float g_Bfrag[NB * NCH * 6 * 32 * 4];   // 1.5 MB

__device__ __forceinline__ uint32_t cvt_tf32(float x) {
    uint32_t u; asm("cvt.rna.tf32.f32 %0, %1;" : "=r"(u) : "f"(x));
    return u;
}

__device__ __forceinline__ void mma_tf32(float (&c)[4], uint32_t a0, uint32_t a1,
                                         uint32_t a2, uint32_t a3,
                                         uint32_t b0, uint32_t b1) {
    asm volatile(
        "mma.sync.aligned.m16n8k8.row.col.f32.tf32.tf32.f32 "
        "{%0,%1,%2,%3}, {%4,%5,%6,%7}, {%8,%9}, {%0,%1,%2,%3};"
        : "+f"(c[0]), "+f"(c[1]), "+f"(c[2]), "+f"(c[3])
        : "r"(a0), "r"(a1), "r"(a2), "r"(a3), "r"(b0), "r"(b1));
}

__device__ __forceinline__ uint32_t f4c(const float4& v, int j) {
    return __float_as_uint(j == 0 ? v.x : j == 1 ? v.y : j == 2 ? v.z : v.w);
}

// ---------------- prologue: build fragment-major B table ----------------
__global__ void __launch_bounds__(256) build_bfrag_kernel(const float* __restrict__ seg) {
    int idx = blockIdx.x * 256 + threadIdx.x;       // 0 .. NB*NCH*6*32*4-1
    int j = idx & 3;
    int l = (idx >> 2) & 31;
    int t = idx >> 7;                               // (b*NCH + c)*6 + f
    int f = t % 6;
    int t2 = t / 6;
    int c = t2 & (NCH - 1);
    int b = t2 >> 7;
    int vidx = 4 * f + j;
    int ks = vidx / 6;
    int rem = vidx - 6 * ks;
    int nt = rem >> 1;
    int r  = rem & 1;
    int gr = l >> 2, tg = l & 3;
    int n = nt * 8 + gr;
    int k = c * KC + ks * 8 + tg + 4 * r;
    float v;
    if (n < ND)       v = __uint_as_float(cvt_tf32(seg[(((size_t)b * ND + n) << 12) + k]));
    else if (n == ND) v = 1.0f;
    else              v = 0.0f;
    g_Bfrag[idx] = v;
}

// ---------------- main kernel ----------------
// grid = 1024 CTAs (4 b x 256 tiles of 16 rows), block = 128 thr = 4 warps.
// All 4 warps cover the SAME 16 rows; warp w owns K quarter [w*1024,(w+1)*1024)
// = 32 chunks. Loop is barrier-free (warp-private smem staging, __syncwarp only);
// partial accumulators are combined via smem once at the end.
__global__ void __launch_bounds__(128, 4) regu_mma_kernel(const float* __restrict__ W,
                                                          float* __restrict__ out) {
    __shared__ __align__(16) float sA[4][2][16 * 32];   // per-warp double buffer (16KB)

    const int tid  = threadIdx.x;
    const int w    = tid >> 5;
    const int lane = tid & 31;
    const int gr   = lane >> 2;
    const int tg   = lane & 3;
    const int b    = blockIdx.x >> 8;
    const int row0 = (blockIdx.x & 255) << 4;
    const int cb   = w * WCH;                  // this warp's first global chunk

    const float* Wp = W + ((size_t)(b * NN + row0)) * NN;
    const float* Bf = g_Bfrag + ((size_t)b * NCH + cb) * 768;

    // W staging coords: q-th LDG covers rows q*4 + (lane>>3), col4 = lane&7
    const int srow = lane >> 3;
    const int sc4  = lane & 7;
    const float* Wq[4];
#pragma unroll
    for (int q = 0; q < 4; ++q)
        Wq[q] = Wp + (size_t)(q * 4 + srow) * NN + cb * KC + sc4 * 4;

    float4 rW[2][4]; float4 rB[2][6];
#pragma unroll
    for (int pp = 0; pp < 2; ++pp) {
#pragma unroll
        for (int q = 0; q < 4; ++q)
            rW[pp][q] = __ldg(reinterpret_cast<const float4*>(Wq[q] + pp * KC));
#pragma unroll
        for (int f = 0; f < 6; ++f)
            rB[pp][f] = __ldg(reinterpret_cast<const float4*>(
                Bf + (size_t)pp * 768 + f * 128 + lane * 4));
    }

    float acc[3][4];
#pragma unroll
    for (int nt = 0; nt < 3; ++nt)
#pragma unroll
        for (int c = 0; c < 4; ++c) acc[nt][c] = 0.0f;

    float* sAw0 = &sA[w][0][0];
    float* sAw1 = &sA[w][1][0];

#pragma unroll 1
    for (int i = 0; i < WCH; ++i) {
        const int p = i & 1;
        float* sb = p ? sAw1 : sAw0;
        // ---- stage chunk i: threshold + tf32 + swizzled STS ----
#pragma unroll
        for (int q = 0; q < 4; ++q) {
            const int row = q * 4 + srow;
            float4 v = rW[p][q];
            uint4 t;
            t.x = cvt_tf32((v.x > THRESH) ? v.x : 0.0f);
            t.y = cvt_tf32((v.y > THRESH) ? v.y : 0.0f);
            t.z = cvt_tf32((v.z > THRESH) ? v.z : 0.0f);
            t.w = cvt_tf32((v.w > THRESH) ? v.w : 0.0f);
            const int phys = row * 32 + ((sc4 ^ (row & 7)) << 2);
            *reinterpret_cast<uint4*>(sb + phys) = t;
        }
        // ---- prefetch W chunk i+2 ----
        if (i + 2 < WCH) {
            const int ko = (i + 2) * KC;
#pragma unroll
            for (int q = 0; q < 4; ++q)
                rW[p][q] = __ldg(reinterpret_cast<const float4*>(Wq[q] + ko));
        }
        __syncwarp();
        // ---- A fragments (swizzled LDS, conflict-free) + MMA ----
#pragma unroll
        for (int ks = 0; ks < 4; ++ks) {
            const int c4a = 2 * ks, c4b = 2 * ks + 1;
            uint32_t a0 = __float_as_uint(sb[gr * 32 + ((c4a ^ gr) << 2) + tg]);
            uint32_t a1 = __float_as_uint(sb[(gr + 8) * 32 + ((c4a ^ gr) << 2) + tg]);
            uint32_t a2 = __float_as_uint(sb[gr * 32 + ((c4b ^ gr) << 2) + tg]);
            uint32_t a3 = __float_as_uint(sb[(gr + 8) * 32 + ((c4b ^ gr) << 2) + tg]);
#pragma unroll
            for (int nt = 0; nt < 3; ++nt) {
                const int v0 = ks * 6 + nt * 2;
                const int v1 = v0 + 1;
                uint32_t b0 = f4c(rB[p][v0 >> 2], v0 & 3);
                uint32_t b1 = f4c(rB[p][v1 >> 2], v1 & 3);
                mma_tf32(acc[nt], a0, a1, a2, a3, b0, b1);
            }
        }
        __syncwarp();
        // ---- prefetch B chunk i+2 (rB[p] fully consumed above) ----
        if (i + 2 < WCH) {
            const float* bp = Bf + (size_t)(i + 2) * 768 + lane * 4;
#pragma unroll
            for (int f = 0; f < 6; ++f)
                rB[p][f] = __ldg(reinterpret_cast<const float4*>(bp + f * 128));
        }
    }

    // ---- combine K-quarter partials across the 4 warps ----
    __syncthreads();                      // all warps done with their staging smem
    float* sred = &sA[0][0][0];           // reuse staging smem: 3*32*12 floats
    if (w > 0) {
        float* dst = sred + ((w - 1) * 32 + lane) * 12;
#pragma unroll
        for (int nt = 0; nt < 3; ++nt)
#pragma unroll
            for (int c = 0; c < 4; ++c) dst[nt * 4 + c] = acc[nt][c];
    }
    __syncthreads();
    if (w == 0) {
#pragma unroll
        for (int src = 0; src < 3; ++src) {
            const float* sp = sred + (src * 32 + lane) * 12;
#pragma unroll
            for (int nt = 0; nt < 3; ++nt)
#pragma unroll
                for (int c = 0; c < 4; ++c) acc[nt][c] += sp[nt * 4 + c];
        }
        // ---- epilogue: divide by ones-column (n=16 -> nt=2, col 0) ----
        // acc[nt][c]: row = gr + (c>=2 ? 8 : 0), col = nt*8 + 2*tg + (c&1)
        const float den_lo = __shfl_sync(0xffffffffu, acc[2][0], lane & ~3);
        const float den_hi = __shfl_sync(0xffffffffu, acc[2][2], lane & ~3);
        const float inv_lo = 1.0f / den_lo;
        const float inv_hi = 1.0f / den_hi;
        float* ob = out + (size_t)b * ND * NN;
#pragma unroll
        for (int nt = 0; nt < 2; ++nt) {
#pragma unroll
            for (int c = 0; c < 4; ++c) {
                int d = nt * 8 + 2 * tg + (c & 1);
                int m = row0 + gr + ((c >= 2) ? 8 : 0);
                ob[(size_t)d * NN + m] = acc[nt][c] * ((c >= 2) ? inv_hi : inv_lo);
            }
        }
    }
}

extern "C" void kernel_launch(void* const* d_in, const int* in_sizes, int n_in,
                              void* d_out, int out_size) {
    const float* seg = (const float*)d_in[0];   // [4,16,64,64] fp32
    const float* W   = (const float*)d_in[1];   // [4,4096,4096] fp32
    float* out = (float*)d_out;                 // [4,16,64,64] fp32
    (void)in_sizes; (void)n_in; (void)out_size;

    build_bfrag_kernel<<<(NB * NCH * 6 * 32 * 4) / 256, 256>>>(seg);
    regu_mma_kernel<<<NB * (NN / 16), 128>>>(W, out);
}

// round 11
// speedup vs baseline: 3.4052x; 2.5379x over previous
#include <cuda_runtime.h>
#include <cstdint>

#define THRESH 0.85f
#define NB 4
#define ND 16
#define NN 4096
#define WCH 16          // k64 chunks per warp (K quarter = 1024)

// A-fragment table (S = tf32(seg), permuted k): [b][c32 0..127][ks 0..3][lane][4]
// entry j for (lane=(gr,tg), ks, c32): row = gr + 8*(j&1),
// physical k = c32*32 + 8*tg + 2*ks + (j>>1). 1 MB, L2-resident.
__device__ float g_Afrag[NB * 128 * 4 * 32 * 4];

__device__ __forceinline__ uint32_t cvt_tf32(float x) {
    uint32_t u; asm("cvt.rna.tf32.f32 %0, %1;" : "=r"(u) : "f"(x));
    return u;
}
__device__ __forceinline__ uint32_t thr(float w) {
    float wt = (w > THRESH) ? w : 0.0f;
    return cvt_tf32(wt);
}
__device__ __forceinline__ void mma_tf32(float (&c)[4], uint32_t a0, uint32_t a1,
                                         uint32_t a2, uint32_t a3,
                                         uint32_t b0, uint32_t b1) {
    asm volatile(
        "mma.sync.aligned.m16n8k8.row.col.f32.tf32.tf32.f32 "
        "{%0,%1,%2,%3}, {%4,%5,%6,%7}, {%8,%9}, {%0,%1,%2,%3};"
        : "+f"(c[0]), "+f"(c[1]), "+f"(c[2]), "+f"(c[3])
        : "r"(a0), "r"(a1), "r"(a2), "r"(a3), "r"(b0), "r"(b1));
}
__device__ __forceinline__ uint32_t fu(float x) { return __float_as_uint(x); }
__device__ __forceinline__ float uf(uint32_t x) { return __uint_as_float(x); }

// ---------------- prologue: build permuted A-fragment table ----------------
__global__ void __launch_bounds__(256) build_afrag_kernel(const float* __restrict__ seg) {
    int idx = blockIdx.x * 256 + threadIdx.x;     // 18-bit index
    int j    = idx & 3;
    int lane = (idx >> 2) & 31;
    int ks   = (idx >> 7) & 3;
    int c    = (idx >> 9) & 127;
    int b    = idx >> 16;
    int gr = lane >> 2, tg = lane & 3;
    int row = gr + 8 * (j & 1);
    int k   = c * 32 + 8 * tg + 2 * ks + (j >> 1);
    g_Afrag[idx] = uf(cvt_tf32(seg[(((size_t)b * ND + row) << 12) + k]));
}

// ---------------- main kernel ----------------
// grid = 1024 CTAs (4 b x 256 tiles of 16 m-rows), block = 128 thr = 4 warps.
// All 4 warps cover the same 16 rows; warp w owns K quarter [w*1024,(w+1)*1024).
// Computes D^T = S @ Wt^T via m16n8k8 tf32 MMA with W as the (thresholded,
// register-resident) B operand. No shared memory in the loop.
__global__ void __launch_bounds__(128, 4) regu_mma_kernel(const float* __restrict__ W,
                                                          float* __restrict__ out) {
    __shared__ float sred[3][32][10];
    const int tid  = threadIdx.x;
    const int w    = tid >> 5;
    const int lane = tid & 31;
    const int gr   = lane >> 2;
    const int tg   = lane & 3;
    const int b    = blockIdx.x >> 8;
    const int m0   = (blockIdx.x & 255) << 4;
    const int kq   = w << 10;

    // B-operand row pointers: lane (gr,tg) reads W row m0+nt*8+gr, its 32B slice 8*tg
    const float* Wb0 = W + ((size_t)(b * NN + m0 + gr)) * NN + kq + 8 * tg;
    const float* Wb1 = Wb0 + (size_t)8 * NN;
    const float* Ab  = g_Afrag + ((size_t)(b * 128 + (kq >> 5)) * 4) * 128 + lane * 4;

    float4 rWa[2][2][2], rWb[2][2][2];    // [nt][h][j]
#pragma unroll
    for (int h = 0; h < 2; ++h)
#pragma unroll
        for (int j = 0; j < 2; ++j) {
            rWa[0][h][j] = __ldg(reinterpret_cast<const float4*>(Wb0 + h * 32 + j * 4));
            rWa[1][h][j] = __ldg(reinterpret_cast<const float4*>(Wb1 + h * 32 + j * 4));
        }

    float acc[2][4] = {{0.f,0.f,0.f,0.f},{0.f,0.f,0.f,0.f}};
    float rs0 = 0.f, rs1 = 0.f;

#define STEP(I_, CUR, NXT)                                                        \
    do {                                                                          \
        const int i_ = (I_);                                                      \
        if (i_ + 1 < WCH) {                                                       \
            const int ko = (i_ + 1) * 64;                                         \
            _Pragma("unroll")                                                     \
            for (int h = 0; h < 2; ++h)                                           \
                _Pragma("unroll")                                                 \
                for (int j = 0; j < 2; ++j) {                                     \
                    NXT[0][h][j] = __ldg(reinterpret_cast<const float4*>(         \
                        Wb0 + ko + h * 32 + j * 4));                              \
                    NXT[1][h][j] = __ldg(reinterpret_cast<const float4*>(         \
                        Wb1 + ko + h * 32 + j * 4));                              \
                }                                                                 \
        }                                                                         \
        _Pragma("unroll")                                                         \
        for (int h = 0; h < 2; ++h) {                                             \
            const float* ap = Ab + (size_t)(2 * i_ + h) * 512;                    \
            float4 A0 = __ldg(reinterpret_cast<const float4*>(ap));               \
            float4 A1 = __ldg(reinterpret_cast<const float4*>(ap + 128));         \
            float4 A2 = __ldg(reinterpret_cast<const float4*>(ap + 256));         \
            float4 A3 = __ldg(reinterpret_cast<const float4*>(ap + 384));         \
            _Pragma("unroll")                                                     \
            for (int nt = 0; nt < 2; ++nt) {                                      \
                float4 f0 = CUR[nt][h][0], f1 = CUR[nt][h][1];                    \
                uint32_t t0 = thr(f0.x), t1 = thr(f0.y);                          \
                uint32_t t2 = thr(f0.z), t3 = thr(f0.w);                          \
                uint32_t t4 = thr(f1.x), t5 = thr(f1.y);                          \
                uint32_t t6 = thr(f1.z), t7 = thr(f1.w);                          \
                float s = ((uf(t0) + uf(t1)) + (uf(t2) + uf(t3))) +               \
                          ((uf(t4) + uf(t5)) + (uf(t6) + uf(t7)));                \
                if (nt == 0) rs0 += s; else rs1 += s;                             \
                mma_tf32(acc[nt], fu(A0.x), fu(A0.y), fu(A0.z), fu(A0.w), t0, t1);\
                mma_tf32(acc[nt], fu(A1.x), fu(A1.y), fu(A1.z), fu(A1.w), t2, t3);\
                mma_tf32(acc[nt], fu(A2.x), fu(A2.y), fu(A2.z), fu(A2.w), t4, t5);\
                mma_tf32(acc[nt], fu(A3.x), fu(A3.y), fu(A3.z), fu(A3.w), t6, t7);\
            }                                                                     \
        }                                                                         \
    } while (0)

#pragma unroll 1
    for (int i = 0; i < WCH; i += 2) {
        STEP(i, rWa, rWb);
        STEP(i + 1, rWb, rWa);
    }
#undef STEP

    // rowsum quad-reduce: all lanes of quad gr end with rs(m = nt*8 + gr)
    rs0 += __shfl_xor_sync(0xffffffffu, rs0, 1);
    rs0 += __shfl_xor_sync(0xffffffffu, rs0, 2);
    rs1 += __shfl_xor_sync(0xffffffffu, rs1, 1);
    rs1 += __shfl_xor_sync(0xffffffffu, rs1, 2);

    // combine K-quarter partials across the 4 warps
    if (w > 0) {
        float* d = sred[w - 1][lane];
#pragma unroll
        for (int nt = 0; nt < 2; ++nt)
#pragma unroll
            for (int c = 0; c < 4; ++c) d[nt * 4 + c] = acc[nt][c];
        d[8] = rs0; d[9] = rs1;
    }
    __syncthreads();
    if (w == 0) {
#pragma unroll
        for (int s = 0; s < 3; ++s) {
            const float* sp = sred[s][lane];
#pragma unroll
            for (int nt = 0; nt < 2; ++nt)
#pragma unroll
                for (int c = 0; c < 4; ++c) acc[nt][c] += sp[nt * 4 + c];
            rs0 += sp[8]; rs1 += sp[9];
        }
        // inverse rowsums for this lane's output columns m-row = 2tg+par
        const float i00 = 1.0f / __shfl_sync(0xffffffffu, rs0, 8 * tg);
        const float i01 = 1.0f / __shfl_sync(0xffffffffu, rs0, 8 * tg + 4);
        const float i10 = 1.0f / __shfl_sync(0xffffffffu, rs1, 8 * tg);
        const float i11 = 1.0f / __shfl_sync(0xffffffffu, rs1, 8 * tg + 4);
        // acc[nt][c]: d = gr + 8*(c>=2), m = m0 + nt*8 + 2tg + (c&1)
        float* ob = out + (size_t)b * ND * NN;
#pragma unroll
        for (int nt = 0; nt < 2; ++nt) {
#pragma unroll
            for (int c = 0; c < 4; ++c) {
                const int dd = gr + ((c >= 2) ? 8 : 0);
                const int m  = m0 + nt * 8 + 2 * tg + (c & 1);
                const float inv = nt ? ((c & 1) ? i11 : i10)
                                     : ((c & 1) ? i01 : i00);
                ob[(size_t)dd * NN + m] = acc[nt][c] * inv;
            }
        }
    }
}

extern "C" void kernel_launch(void* const* d_in, const int* in_sizes, int n_in,
                              void* d_out, int out_size) {
    const float* seg = (const float*)d_in[0];   // [4,16,64,64] fp32
    const float* W   = (const float*)d_in[1];   // [4,4096,4096] fp32
    float* out = (float*)d_out;                 // [4,16,64,64] fp32
    (void)in_sizes; (void)n_in; (void)out_size;

    build_afrag_kernel<<<(NB * 128 * 4 * 32 * 4) / 256, 256>>>(seg);
    regu_mma_kernel<<<NB * (NN / 16), 128>>>(W, out);
}